// round 2
// baseline (speedup 1.0000x reference)
#include <cuda_runtime.h>
#include <cstdint>

#define B_SZ   8192
#define IN_DIMS 784
#define NETS   30
#define NODES  20
#define OUTC   10
#define DIMK   16
#define H1C    (NETS * NODES)   // 600

// ---------------- scratch (device globals; no allocations) ----------------
__device__ float g_W1p[IN_DIMS * H1C];              // 1.88 MB packed W1 [i][n*20+o]
__device__ float g_h1[(size_t)B_SZ * H1C];          // 19.7 MB
__device__ float g_u [(size_t)B_SZ * H1C];          // 19.7 MB

// ---------------- f32x2 helpers (Blackwell packed fp32) --------------------
__device__ __forceinline__ unsigned long long pack2(float lo, float hi) {
    unsigned long long r;
    asm("mov.b64 %0, {%1, %2};" : "=l"(r) : "f"(lo), "f"(hi));
    return r;
}
__device__ __forceinline__ void fma2(unsigned long long& d, unsigned long long a, unsigned long long b) {
    asm("fma.rn.f32x2 %0, %1, %2, %0;" : "+l"(d) : "l"(a), "l"(b));
}
__device__ __forceinline__ void unpack2(unsigned long long v, float& lo, float& hi) {
    asm("mov.b64 {%0, %1}, %2;" : "=f"(lo), "=f"(hi) : "l"(v));
}

// ---------------- kernel 0: pack W1 [n][i][o] -> [i][n*20+o] ---------------
__global__ void k_pack(const float* __restrict__ W1) {
    int total = IN_DIMS * H1C;
    for (int i = blockIdx.x * blockDim.x + threadIdx.x; i < total;
         i += gridDim.x * blockDim.x) {
        int row = i / H1C;          // input feature
        int col = i % H1C;          // n*20+o
        int n = col / NODES, o = col % NODES;
        g_W1p[i] = W1[(n * IN_DIMS + row) * NODES + o];
    }
}

// ---------------- kernel 1: h1 = relu(x @ W1p + b1) ------------------------
// C[8192,600] = A[8192,784] x B[784,600]; BM=128 BN=64 BK=8, 256 thr,
// per-thread 8x4 microtile as 8x2 f32x2 accumulators.
#define BM 128
#define BN 64
#define BK 8

__global__ __launch_bounds__(256)
void k_gemm1(const float* __restrict__ X, const float* __restrict__ b1) {
    __shared__ float As[BK][BM];
    __shared__ float Bs[BK][BN];

    const int tid  = threadIdx.x;
    const int tx   = tid & 15;          // N dir (16 x 4 cols)
    const int ty   = tid >> 4;          // M dir (16 x 8 rows)
    const int m0   = blockIdx.y * BM;
    const int col0 = blockIdx.x * BN;

    // A load: one float4 per thread (row = tid/2, 4 cols)
    const int a_row = tid >> 1;
    const int a_c4  = (tid & 1) * 4;
    // B load: two floats per thread
    const int b_r = tid >> 5;           // 0..7
    const int b_c = (tid & 31) * 2;     // 0..62

    unsigned long long acc[8][2];
#pragma unroll
    for (int i = 0; i < 8; i++) { acc[i][0] = 0ull; acc[i][1] = 0ull; }

    for (int kt = 0; kt < IN_DIMS; kt += BK) {
        float4 av = *(const float4*)(X + (m0 + a_row) * IN_DIMS + kt + a_c4);
        As[a_c4 + 0][a_row] = av.x;
        As[a_c4 + 1][a_row] = av.y;
        As[a_c4 + 2][a_row] = av.z;
        As[a_c4 + 3][a_row] = av.w;

        int gc = col0 + b_c;
        float bx = (gc     < H1C) ? g_W1p[(kt + b_r) * H1C + gc]     : 0.f;
        float by = (gc + 1 < H1C) ? g_W1p[(kt + b_r) * H1C + gc + 1] : 0.f;
        Bs[b_r][b_c]     = bx;
        Bs[b_r][b_c + 1] = by;
        __syncthreads();

#pragma unroll
        for (int k = 0; k < BK; k++) {
            float4 a0 = *(const float4*)&As[k][ty * 8];
            float4 a1 = *(const float4*)&As[k][ty * 8 + 4];
            float4 bv = *(const float4*)&Bs[k][tx * 4];
            unsigned long long bp0 = pack2(bv.x, bv.y);
            unsigned long long bp1 = pack2(bv.z, bv.w);
            float am[8] = {a0.x, a0.y, a0.z, a0.w, a1.x, a1.y, a1.z, a1.w};
#pragma unroll
            for (int i = 0; i < 8; i++) {
                unsigned long long ap = pack2(am[i], am[i]);
                fma2(acc[i][0], ap, bp0);
                fma2(acc[i][1], ap, bp1);
            }
        }
        __syncthreads();
    }

#pragma unroll
    for (int i = 0; i < 8; i++) {
        int row = m0 + ty * 8 + i;
        float c[4];
        unpack2(acc[i][0], c[0], c[1]);
        unpack2(acc[i][1], c[2], c[3]);
#pragma unroll
        for (int j = 0; j < 4; j++) {
            int col = col0 + tx * 4 + j;
            if (col < H1C)
                g_h1[(size_t)row * H1C + col] = fmaxf(c[j] + b1[col], 0.f);
        }
    }
}

// ---------------- kernel 2: h2 = relu(h1@W2+b2); u = squash(h2) -----------
// one warp per (b, net); lanes 0..19 = output feature e.
__global__ __launch_bounds__(256)
void k_h2u(const float* __restrict__ W2, const float* __restrict__ b2) {
    extern __shared__ float sh[];
    float* W2s = sh;            // 12000 floats
    float* b2s = sh + NETS * NODES * NODES;  // 600 floats

    for (int i = threadIdx.x; i < NETS * NODES * NODES; i += blockDim.x)
        W2s[i] = W2[i];
    for (int i = threadIdx.x; i < NETS * NODES; i += blockDim.x)
        b2s[i] = b2[i];
    __syncthreads();

    const int lane  = threadIdx.x & 31;
    const int warp  = threadIdx.x >> 5;
    const int gw    = blockIdx.x * (blockDim.x >> 5) + warp;
    const int nwarp = gridDim.x * (blockDim.x >> 5);
    const int e     = (lane < NODES) ? lane : 0;
    const bool act  = lane < NODES;

    for (int t = gw; t < B_SZ * NETS; t += nwarp) {
        int b = t / NETS, n = t % NETS;
        float acc = act ? b2s[n * NODES + e] : 0.f;
        const float* h1row = g_h1 + (size_t)b * H1C + n * NODES;
#pragma unroll
        for (int d = 0; d < NODES; d++) {
            float hv = __ldg(h1row + d);
            acc = fmaf(hv, W2s[(n * NODES + d) * NODES + e], acc);
        }
        float h = act ? fmaxf(acc, 0.f) : 0.f;
        float sq = h * h;
#pragma unroll
        for (int off = 16; off > 0; off >>= 1)
            sq += __shfl_xor_sync(0xffffffffu, sq, off);
        float scale = (sq / (1.f + sq)) * rsqrtf(sq);   // matches ref (NaN iff ref NaN)
        if (act)
            g_u[(size_t)b * H1C + n * NODES + e] = h * scale;
    }
}

// ---------------- kernel 3: priors + 3 routing iterations (fused) ----------
// CTA handles TB=8 batch rows; priors held entirely in shared memory.
#define TB 8
#define RT_THREADS 256

__global__ __launch_bounds__(RT_THREADS)
void k_route(const float* __restrict__ RW, float* __restrict__ out) {
    extern __shared__ float sh[];
    float* u_s     = sh;                          // TB*600        = 4800
    float* p_s     = u_s     + TB * H1C;          // TB*10*30*16   = 38400
    float* logit_s = p_s     + TB * OUTC * NETS * DIMK;  // TB*10*30 = 2400
    float* prob_s  = logit_s + TB * OUTC * NETS;  // 2400
    float* v_s     = prob_s  + TB * OUTC * NETS;  // TB*10*16 = 1280
    float* nrm_s   = v_s     + TB * OUTC * DIMK;  // TB*10 = 80

    const int tid  = threadIdx.x;
    const int b0   = blockIdx.x * TB;

    // load u tile (contiguous)
    for (int i = tid; i < TB * H1C; i += RT_THREADS)
        u_s[i] = g_u[(size_t)b0 * H1C + i];
    // init logits / probs (softmax of zeros = 0.1)
    for (int i = tid; i < TB * OUTC * NETS; i += RT_THREADS) {
        logit_s[i] = 0.f;
        prob_s[i]  = 0.1f;
    }
    __syncthreads();

    // ---- priors: p[b][o][n][k] = sum_d u[b][n][d] * RW[o][n][d][k]
    const int warp = tid >> 5;
    const int lane = tid & 31;
    const int bb   = lane >> 4;      // 0..1
    const int k    = lane & 15;      // 0..15
    for (int p = warp; p < OUTC * NETS; p += (RT_THREADS >> 5)) {
        int o = p / NETS, n = p % NETS;
        const float* rw = RW + ((size_t)(o * NETS + n) * NODES) * DIMK;
        float rwreg[NODES];
#pragma unroll
        for (int d = 0; d < NODES; d++) rwreg[d] = __ldg(rw + d * DIMK + k);
#pragma unroll
        for (int bq = 0; bq < TB / 2; bq++) {
            int b = bq * 2 + bb;
            const float* ub = u_s + b * H1C + n * NODES;
            float acc = 0.f;
#pragma unroll
            for (int d = 0; d < NODES; d++) acc = fmaf(ub[d], rwreg[d], acc);
            p_s[((b * OUTC + o) * NETS + n) * DIMK + k] = acc;
        }
    }
    __syncthreads();

    // ---- routing: 3 iterations
    for (int it = 0; it < 3; it++) {
        // s[b][o][k] = sum_n prob[b][o][n] * p[b][o][n][k]   (into v_s)
        for (int t = tid; t < TB * OUTC * DIMK; t += RT_THREADS) {
            int b = t / (OUTC * DIMK);
            int o = (t / DIMK) % OUTC;
            int kk = t % DIMK;
            const float* pr = prob_s + (b * OUTC + o) * NETS;
            const float* pp = p_s + ((b * OUTC + o) * NETS) * DIMK + kk;
            float s = 0.f;
#pragma unroll
            for (int n = 0; n < NETS; n++) s = fmaf(pr[n], pp[n * DIMK], s);
            v_s[t] = s;
        }
        __syncthreads();
        // squash norms per (b,o)
        for (int t = tid; t < TB * OUTC; t += RT_THREADS) {
            const float* v = v_s + t * DIMK;
            float sq = 0.f;
#pragma unroll
            for (int kk = 0; kk < DIMK; kk++) sq = fmaf(v[kk], v[kk], sq);
            nrm_s[t] = (sq / (1.f + sq)) * rsqrtf(sq);
        }
        __syncthreads();
        for (int t = tid; t < TB * OUTC * DIMK; t += RT_THREADS)
            v_s[t] *= nrm_s[t / DIMK];
        __syncthreads();

        if (it < 2) {
            // logits += sum_k p[b][o][n][k] * v[b][o][k]
            for (int t = tid; t < TB * OUTC * NETS; t += RT_THREADS) {
                int b = t / (OUTC * NETS);
                int o = (t / NETS) % OUTC;
                int n = t % NETS;
                const float* pp = p_s + ((b * OUTC + o) * NETS + n) * DIMK;
                const float* v  = v_s + (b * OUTC + o) * DIMK;
                float dot = 0.f;
#pragma unroll
                for (int kk = 0; kk < DIMK; kk++) dot = fmaf(pp[kk], v[kk], dot);
                logit_s[t] += dot;
            }
            __syncthreads();
            // probs = softmax over o, per (b, n)
            for (int t = tid; t < TB * NETS; t += RT_THREADS) {
                int b = t / NETS, n = t % NETS;
                float m = -1e30f;
#pragma unroll
                for (int o = 0; o < OUTC; o++)
                    m = fmaxf(m, logit_s[(b * OUTC + o) * NETS + n]);
                float ssum = 0.f;
                float e[OUTC];
#pragma unroll
                for (int o = 0; o < OUTC; o++) {
                    e[o] = __expf(logit_s[(b * OUTC + o) * NETS + n] - m);
                    ssum += e[o];
                }
                float inv = 1.f / ssum;
#pragma unroll
                for (int o = 0; o < OUTC; o++)
                    prob_s[(b * OUTC + o) * NETS + n] = e[o] * inv;
            }
            __syncthreads();
        }
    }

    // ---- write output [B, 10, 16]; v_s is exactly the contiguous chunk
    for (int t = tid; t < TB * OUTC * DIMK; t += RT_THREADS)
        out[(size_t)b0 * OUTC * DIMK + t] = v_s[t];
}

// ---------------- launcher -------------------------------------------------
extern "C" void kernel_launch(void* const* d_in, const int* in_sizes, int n_in,
                              void* d_out, int out_size) {
    const float* x  = (const float*)d_in[0];
    const float* W1 = (const float*)d_in[1];
    const float* b1 = (const float*)d_in[2];
    const float* W2 = (const float*)d_in[3];
    const float* b2 = (const float*)d_in[4];
    const float* RW = (const float*)d_in[5];
    float* out = (float*)d_out;

    // shared-memory attribute opt-ins (idempotent, capture-safe)
    static const size_t smem_h2u   = (size_t)(NETS * NODES * NODES + NETS * NODES) * 4;
    static const size_t smem_route = (size_t)(TB * H1C + TB * OUTC * NETS * DIMK +
                                              2 * TB * OUTC * NETS +
                                              TB * OUTC * DIMK + TB * OUTC) * 4;
    cudaFuncSetAttribute(k_h2u,   cudaFuncAttributeMaxDynamicSharedMemorySize, (int)smem_h2u);
    cudaFuncSetAttribute(k_route, cudaFuncAttributeMaxDynamicSharedMemorySize, (int)smem_route);

    k_pack<<<512, 256>>>(W1);
    dim3 g1((H1C + BN - 1) / BN, B_SZ / BM);
    k_gemm1<<<g1, 256>>>(x, b1);
    k_h2u<<<1024, 256, smem_h2u>>>(W2, b2);
    k_route<<<B_SZ / TB, RT_THREADS, smem_route>>>(RW, out);
}

// round 5
// speedup vs baseline: 1.0804x; 1.0804x over previous
#include <cuda_runtime.h>
#include <cstdint>

#define B_SZ    8192
#define IN_DIMS 784
#define NETS    30
#define NODES   20
#define OUTC    10
#define DIMK    16
#define H1C     (NETS * NODES)   // 600

// ---------------- scratch (device globals; no allocations) ----------------
__device__ float g_W1p[IN_DIMS * H1C];              // packed W1 [i][n*20+o]
__device__ float g_h1[(size_t)B_SZ * H1C];
__device__ float g_u [(size_t)B_SZ * H1C];

// ---------------- f32x2 helpers (Blackwell packed fp32) --------------------
__device__ __forceinline__ unsigned long long pack2(float lo, float hi) {
    unsigned long long r;
    asm("mov.b64 %0, {%1, %2};" : "=l"(r) : "f"(lo), "f"(hi));
    return r;
}
__device__ __forceinline__ void fma2(unsigned long long& d, unsigned long long a, unsigned long long b) {
    asm("fma.rn.f32x2 %0, %1, %2, %0;" : "+l"(d) : "l"(a), "l"(b));
}
__device__ __forceinline__ void unpack2(unsigned long long v, float& lo, float& hi) {
    asm("mov.b64 {%0, %1}, %2;" : "=f"(lo), "=f"(hi) : "l"(v));
}

// ---------------- kernel 0: pack W1 [n][i][o] -> [i][n*20+o] ---------------
__global__ void k_pack(const float* __restrict__ W1) {
    int total = IN_DIMS * H1C;
    for (int i = blockIdx.x * blockDim.x + threadIdx.x; i < total;
         i += gridDim.x * blockDim.x) {
        int row = i / H1C;
        int col = i - row * H1C;
        int n = col / NODES, o = col - n * NODES;
        g_W1p[i] = W1[(n * IN_DIMS + row) * NODES + o];
    }
}

// ---------------- kernel 1: h1 = relu(x @ W1p + b1) ------------------------
// C[8192,600] = A[8192,784] x B[784,600]; BM=128 BN=128 BK=8, 256 thr,
// per-thread 8x8 microtile as 8x4 f32x2 accumulators, double-buffered smem.
#define BM 128
#define BN 128
#define BK 8

__global__ __launch_bounds__(256, 2)
void k_gemm1(const float* __restrict__ X, const float* __restrict__ b1) {
    __shared__ float As[2][BK][BM];
    __shared__ float Bs[2][BK][BN];

    const int tid  = threadIdx.x;
    const int tx   = tid & 15;          // N dir: col group tx*8
    const int ty   = tid >> 4;          // M dir: row group ty*8
    const int m0   = blockIdx.y * BM;
    const int col0 = blockIdx.x * BN;

    // A load: float4 per thread; pair of threads covers one row's 8 k's
    const int a_row = tid >> 1;
    const int a_c4  = (tid & 1) * 4;
    // B load: float4 per thread along columns
    const int b_r   = tid >> 5;          // 0..7 (k)
    const int b_c4  = (tid & 31) * 4;    // 0..124
    const int bcol  = col0 + b_c4;
    const bool bvalid = (bcol < H1C);

    // stage 0
    {
        float4 av = *(const float4*)(X + (size_t)(m0 + a_row) * IN_DIMS + a_c4);
        As[0][a_c4 + 0][a_row] = av.x;
        As[0][a_c4 + 1][a_row] = av.y;
        As[0][a_c4 + 2][a_row] = av.z;
        As[0][a_c4 + 3][a_row] = av.w;
        float4 bv = bvalid ? *(const float4*)(g_W1p + (size_t)b_r * H1C + bcol)
                           : make_float4(0.f, 0.f, 0.f, 0.f);
        *(float4*)&Bs[0][b_r][b_c4] = bv;
    }
    __syncthreads();

    unsigned long long acc[8][4];
#pragma unroll
    for (int i = 0; i < 8; i++)
#pragma unroll
        for (int j = 0; j < 4; j++) acc[i][j] = 0ull;

    int buf = 0;
    for (int kt = 0; kt < IN_DIMS; kt += BK) {
        float4 aP, bP;
        const bool more = (kt + BK) < IN_DIMS;
        if (more) {
            aP = *(const float4*)(X + (size_t)(m0 + a_row) * IN_DIMS + kt + BK + a_c4);
            bP = bvalid ? *(const float4*)(g_W1p + (size_t)(kt + BK + b_r) * H1C + bcol)
                        : make_float4(0.f, 0.f, 0.f, 0.f);
        }
#pragma unroll
        for (int kk = 0; kk < BK; kk++) {
            float4 a0 = *(const float4*)&As[buf][kk][ty * 8];
            float4 a1 = *(const float4*)&As[buf][kk][ty * 8 + 4];
            float4 q0 = *(const float4*)&Bs[buf][kk][tx * 8];
            float4 q1 = *(const float4*)&Bs[buf][kk][tx * 8 + 4];
            unsigned long long bp0 = pack2(q0.x, q0.y);
            unsigned long long bp1 = pack2(q0.z, q0.w);
            unsigned long long bp2 = pack2(q1.x, q1.y);
            unsigned long long bp3 = pack2(q1.z, q1.w);
            float am[8] = {a0.x, a0.y, a0.z, a0.w, a1.x, a1.y, a1.z, a1.w};
#pragma unroll
            for (int i = 0; i < 8; i++) {
                unsigned long long ap = pack2(am[i], am[i]);
                fma2(acc[i][0], ap, bp0);
                fma2(acc[i][1], ap, bp1);
                fma2(acc[i][2], ap, bp2);
                fma2(acc[i][3], ap, bp3);
            }
        }
        if (more) {
            As[buf ^ 1][a_c4 + 0][a_row] = aP.x;
            As[buf ^ 1][a_c4 + 1][a_row] = aP.y;
            As[buf ^ 1][a_c4 + 2][a_row] = aP.z;
            As[buf ^ 1][a_c4 + 3][a_row] = aP.w;
            *(float4*)&Bs[buf ^ 1][b_r][b_c4] = bP;
            __syncthreads();
            buf ^= 1;
        }
    }

    // epilogue: bias + relu + store (8 cols per thread = two float4 groups)
    const int c0 = col0 + tx * 8;
    const bool cvalid = (c0 < H1C);     // 600 % 8 == 0 => whole group valid or not
    float bias[8];
    if (cvalid) {
#pragma unroll
        for (int j = 0; j < 8; j++) bias[j] = __ldg(b1 + c0 + j);
    }
#pragma unroll
    for (int i = 0; i < 8; i++) {
        int row = m0 + ty * 8 + i;
        float c[8];
        unpack2(acc[i][0], c[0], c[1]);
        unpack2(acc[i][1], c[2], c[3]);
        unpack2(acc[i][2], c[4], c[5]);
        unpack2(acc[i][3], c[6], c[7]);
        if (cvalid) {
#pragma unroll
            for (int j = 0; j < 8; j++) c[j] = fmaxf(c[j] + bias[j], 0.f);
            float* dst = g_h1 + (size_t)row * H1C + c0;
            *(float4*)dst       = make_float4(c[0], c[1], c[2], c[3]);
            *(float4*)(dst + 4) = make_float4(c[4], c[5], c[6], c[7]);
        }
    }
}

// ---------------- kernel 2: h2 = relu(h1@W2+b2); u = squash(h2) -----------
__global__ __launch_bounds__(256)
void k_h2u(const float* __restrict__ W2, const float* __restrict__ b2) {
    extern __shared__ float sh[];
    float* W2s = sh;                           // 12000 floats
    float* b2s = sh + NETS * NODES * NODES;    // 600 floats

    for (int i = threadIdx.x; i < NETS * NODES * NODES; i += blockDim.x)
        W2s[i] = W2[i];
    for (int i = threadIdx.x; i < NETS * NODES; i += blockDim.x)
        b2s[i] = b2[i];
    __syncthreads();

    const int lane  = threadIdx.x & 31;
    const int warp  = threadIdx.x >> 5;
    const int gw    = blockIdx.x * (blockDim.x >> 5) + warp;
    const int nwarp = gridDim.x * (blockDim.x >> 5);
    const int e     = (lane < NODES) ? lane : 0;
    const bool act  = lane < NODES;

    for (int t = gw; t < B_SZ * NETS; t += nwarp) {
        int b = t / NETS, n = t - b * NETS;
        float acc = act ? b2s[n * NODES + e] : 0.f;
        const float4* h4 = (const float4*)(g_h1 + (size_t)b * H1C + n * NODES);
        float hv[NODES];
#pragma unroll
        for (int q = 0; q < NODES / 4; q++) {
            float4 v = __ldg(h4 + q);
            hv[q * 4 + 0] = v.x; hv[q * 4 + 1] = v.y;
            hv[q * 4 + 2] = v.z; hv[q * 4 + 3] = v.w;
        }
#pragma unroll
        for (int d = 0; d < NODES; d++)
            acc = fmaf(hv[d], W2s[(n * NODES + d) * NODES + e], acc);
        float h = act ? fmaxf(acc, 0.f) : 0.f;
        float sq = h * h;
#pragma unroll
        for (int off = 16; off > 0; off >>= 1)
            sq += __shfl_xor_sync(0xffffffffu, sq, off);
        float scale = (sq / (1.f + sq)) * rsqrtf(sq);
        if (act)
            g_u[(size_t)b * H1C + n * NODES + e] = h * scale;
    }
}

// ---------------- kernel 3: priors + routing, warp-per-output-capsule ------
// 10 warps = 10 output capsules o; lanes = (half = n parity, k).
// TB=4 batch rows/CTA; priors in smem [b][o][n][k]; reductions via shuffles.
#define TB 4
#define RTHREADS 320   // 10 warps

__global__ __launch_bounds__(RTHREADS, 2)
void k_route(const float* __restrict__ RW, float* __restrict__ out) {
    extern __shared__ float sh[];
    float* u_s     = sh;                                   // TB*600
    float* p_s     = u_s + TB * H1C;                       // TB*4800
    float* logit_s = p_s + TB * OUTC * NETS * DIMK;        // TB*300
    float* prob_s  = logit_s + TB * OUTC * NETS;           // TB*300

    const int tid  = threadIdx.x;
    const int o    = tid >> 5;          // warp = output capsule
    const int lane = tid & 31;
    const int k    = lane & 15;
    const int half = lane >> 4;
    const int b0   = blockIdx.x * TB;

    for (int i = tid; i < TB * H1C; i += RTHREADS)
        u_s[i] = g_u[(size_t)b0 * H1C + i];
    __syncthreads();

    // ---- priors: warp o computes p[b][o][n][k]; half handles n of its parity
    const int pbase = o * (NETS * DIMK) + k;
#pragma unroll 1
    for (int ni = 0; ni < NETS / 2; ni++) {
        const int n = 2 * ni + half;
        const float* rw = RW + ((size_t)(o * NETS + n) * NODES) * DIMK + k;
        float rwreg[NODES];
#pragma unroll
        for (int d = 0; d < NODES; d++) rwreg[d] = __ldg(rw + d * DIMK);
#pragma unroll
        for (int b = 0; b < TB; b++) {
            const float* ub = u_s + b * H1C + n * NODES;
            float acc = 0.f;
#pragma unroll
            for (int d = 0; d < NODES; d++) acc = fmaf(ub[d], rwreg[d], acc);
            p_s[b * (OUTC * NETS * DIMK) + pbase + n * DIMK] = acc;
        }
    }
    // no barrier needed: each warp reads back only its own o-slice

    float v[TB];
#pragma unroll 1
    for (int it = 0; it < 3; it++) {
        // s[b][o][k] = sum_n prob * p; halves sum their parity, combine via xor16
#pragma unroll
        for (int b = 0; b < TB; b++) {
            const float* pb  = p_s + b * (OUTC * NETS * DIMK) + pbase;
            const float* prb = prob_s + b * (OUTC * NETS) + o * NETS;
            float s = 0.f;
            if (it == 0) {
#pragma unroll
                for (int ni = 0; ni < NETS / 2; ni++)
                    s += pb[(2 * ni + half) * DIMK];
                s *= 0.1f;   // softmax of zeros
            } else {
#pragma unroll
                for (int ni = 0; ni < NETS / 2; ni++) {
                    const int n = 2 * ni + half;
                    s = fmaf(prb[n], pb[n * DIMK], s);
                }
            }
            s += __shfl_xor_sync(0xffffffffu, s, 16);
            float sq = s * s;
            sq += __shfl_xor_sync(0xffffffffu, sq, 1);
            sq += __shfl_xor_sync(0xffffffffu, sq, 2);
            sq += __shfl_xor_sync(0xffffffffu, sq, 4);
            sq += __shfl_xor_sync(0xffffffffu, sq, 8);
            v[b] = s * (sq / (1.f + sq)) * rsqrtf(sq);
        }

        if (it < 2) {
            // logits[b][o][n] (+)= sum_k p[b][o][n][k] * v[b][o][k]
#pragma unroll
            for (int b = 0; b < TB; b++) {
                const float* pb = p_s + b * (OUTC * NETS * DIMK) + pbase;
                float* lg = logit_s + b * (OUTC * NETS) + o * NETS;
#pragma unroll
                for (int ni = 0; ni < NETS / 2; ni++) {
                    const int n = 2 * ni + half;
                    float t = pb[n * DIMK] * v[b];
                    t += __shfl_xor_sync(0xffffffffu, t, 1);
                    t += __shfl_xor_sync(0xffffffffu, t, 2);
                    t += __shfl_xor_sync(0xffffffffu, t, 4);
                    t += __shfl_xor_sync(0xffffffffu, t, 8);
                    if (k == 0) lg[n] = (it == 0) ? t : (lg[n] + t);
                }
            }
            __syncthreads();
            // softmax over o per (b, n)
            for (int t = tid; t < TB * NETS; t += RTHREADS) {
                const int b = t / NETS, n = t - b * NETS;
                const float* lg = logit_s + b * (OUTC * NETS) + n;
                float m = -1e30f;
#pragma unroll
                for (int oo = 0; oo < OUTC; oo++)
                    m = fmaxf(m, lg[oo * NETS]);
                float e[OUTC], ssum = 0.f;
#pragma unroll
                for (int oo = 0; oo < OUTC; oo++) {
                    e[oo] = __expf(lg[oo * NETS] - m);
                    ssum += e[oo];
                }
                float inv = 1.f / ssum;
                float* pr = prob_s + b * (OUTC * NETS) + n;
#pragma unroll
                for (int oo = 0; oo < OUTC; oo++)
                    pr[oo * NETS] = e[oo] * inv;
            }
            __syncthreads();
        }
    }

    // output [B,10,16]; both halves hold identical v, half 0 stores
    if (half == 0) {
#pragma unroll
        for (int b = 0; b < TB; b++)
            out[((size_t)(b0 + b) * OUTC + o) * DIMK + k] = v[b];
    }
}

// ---------------- launcher -------------------------------------------------
extern "C" void kernel_launch(void* const* d_in, const int* in_sizes, int n_in,
                              void* d_out, int out_size) {
    const float* x  = (const float*)d_in[0];
    const float* W1 = (const float*)d_in[1];
    const float* b1 = (const float*)d_in[2];
    const float* W2 = (const float*)d_in[3];
    const float* b2 = (const float*)d_in[4];
    const float* RW = (const float*)d_in[5];
    float* out = (float*)d_out;

    static const size_t smem_h2u   = (size_t)(NETS * NODES * NODES + NETS * NODES) * 4;
    static const size_t smem_route = (size_t)(TB * H1C + TB * OUTC * NETS * DIMK +
                                              2 * TB * OUTC * NETS) * 4;
    cudaFuncSetAttribute(k_h2u,   cudaFuncAttributeMaxDynamicSharedMemorySize, (int)smem_h2u);
    cudaFuncSetAttribute(k_route, cudaFuncAttributeMaxDynamicSharedMemorySize, (int)smem_route);

    k_pack<<<512, 256>>>(W1);
    dim3 g1((H1C + BN - 1) / BN, B_SZ / BM);
    k_gemm1<<<g1, 256>>>(x, b1);
    k_h2u<<<1024, 256, smem_h2u>>>(W2, b2);
    k_route<<<B_SZ / TB, RTHREADS, smem_route>>>(RW, out);
}